// round 8
// baseline (speedup 1.0000x reference)
#include <cuda_runtime.h>
#include <math.h>

// Problem shape (fixed by the dataset)
#define T_DIM 2048
#define N_DIM 64
#define D_DIM 1024
#define TN    (T_DIM * N_DIM)      // 131072 (t,n) slots

#define NCTA 304                    // 152 SMs x occ 2 -> single persistent wave
#define WPB  8
#define GSTRIDE (NCTA * WPB)        // 2432 warps striding the flattened domain

#define EPS 1e-6f
#define LOG_EPS -13.8155106f        // log(1e-6)
#define Z_CLAMP -13.8155121f        // below this, sigmoid(z) < eps
#define HALF_LOG_2PI 0.9189385332046727f

__global__ void zero_out_kernel(float* __restrict__ out, int n) {
    int i = blockIdx.x * blockDim.x + threadIdx.x;
    if (i < n) out[i] = 0.0f;
}

// Persistent single-wave kernel. Work item = flattened slot j = n*2048 + t.
// Warp w processes j = w, w+2432, ... skipping invalid slots (t >= lens[n])
// via an smem lens probe (no DRAM traffic for masked rows). Full next row
// (8 independent LDG.128 + y) is prefetched before the current row's
// FMA/shfl/MUFU tail. No __syncthreads after init, one RED.ADD per row.
__global__ __launch_bounds__(256, 2)
void gaussian_nll_kernel(const float* __restrict__ y,
                         const float* __restrict__ x,
                         const float* __restrict__ W,
                         const int* __restrict__ lens,
                         float* __restrict__ out) {
    __shared__ int slens[N_DIM];
    if (threadIdx.x < N_DIM) slens[threadIdx.x] = lens[threadIdx.x];
    __syncthreads();

    const int warp = threadIdx.x >> 5;
    const int lane = threadIdx.x & 31;
    const int w    = blockIdx.x * WPB + warp;

    const float4* __restrict__ w0 = reinterpret_cast<const float4*>(W);
    const float4* __restrict__ w1 = reinterpret_cast<const float4*>(W + D_DIM);

    // j -> (t = j & 2047, n = j >> 11); valid iff t < lens[n]
    int j = w;
    while (j < TN && (j & 2047) >= slens[j >> 11]) j += GSTRIDE;
    if (j >= TN) return;   // warp-uniform; no block sync below

    // Prime the pipeline with the first valid row
    float4 cur[8];
    float  ycur = 0.0f;
    {
        const int t = j & 2047, n = j >> 11;
        const float4* __restrict__ xr =
            reinterpret_cast<const float4*>(x + ((size_t)(t * N_DIM + n) << 10));
        #pragma unroll
        for (int i = 0; i < 8; i++) cur[i] = xr[i * 32 + lane];
        if (lane == 0) ycur = __ldg(&y[t * N_DIM + n]);
    }

    while (true) {
        // ---- Find + prefetch next valid row (in flight during compute) ----
        int jn = j + GSTRIDE;
        while (jn < TN && (jn & 2047) >= slens[jn >> 11]) jn += GSTRIDE;
        const bool have_next = jn < TN;

        float4 nxt[8];
        float  ynxt = 0.0f;
        if (have_next) {
            const int tn = jn & 2047, nn = jn >> 11;
            const float4* __restrict__ xrn =
                reinterpret_cast<const float4*>(x + ((size_t)(tn * N_DIM + nn) << 10));
            #pragma unroll
            for (int i = 0; i < 8; i++) nxt[i] = xrn[i * 32 + lane];
            if (lane == 0) ynxt = __ldg(&y[tn * N_DIM + nn]);
        }

        // ---- Current row: two dots, dual accumulators ----
        float d0a = 0.0f, d0b = 0.0f, d1a = 0.0f, d1b = 0.0f;
        #pragma unroll
        for (int i = 0; i < 8; i += 2) {
            const int i0 = i * 32 + lane, i1 = (i + 1) * 32 + lane;
            float4 a0 = __ldg(&w0[i0]), b0 = __ldg(&w1[i0]);   // L1 hits (8 KB)
            float4 a1 = __ldg(&w0[i1]), b1 = __ldg(&w1[i1]);
            d0a = fmaf(cur[i].x, a0.x, fmaf(cur[i].y, a0.y,
                  fmaf(cur[i].z, a0.z, fmaf(cur[i].w, a0.w, d0a))));
            d1a = fmaf(cur[i].x, b0.x, fmaf(cur[i].y, b0.y,
                  fmaf(cur[i].z, b0.z, fmaf(cur[i].w, b0.w, d1a))));
            d0b = fmaf(cur[i+1].x, a1.x, fmaf(cur[i+1].y, a1.y,
                  fmaf(cur[i+1].z, a1.z, fmaf(cur[i+1].w, a1.w, d0b))));
            d1b = fmaf(cur[i+1].x, b1.x, fmaf(cur[i+1].y, b1.y,
                  fmaf(cur[i+1].z, b1.z, fmaf(cur[i+1].w, b1.w, d1b))));
        }
        const float d0 = d0a + d0b, d1 = d1a + d1b;

        // ---- 7-shfl dual reduction: fold d0/d1 after the xor-16 step ----
        const float v0 = d0 + __shfl_xor_sync(0xFFFFFFFFu, d0, 16);
        const float v1 = d1 + __shfl_xor_sync(0xFFFFFFFFu, d1, 16);
        float s = (lane < 16) ? v0 : v1;
        #pragma unroll
        for (int off = 8; off > 0; off >>= 1)
            s += __shfl_xor_sync(0xFFFFFFFFu, s, off);
        const float zfull = __shfl_sync(0xFFFFFFFFu, s, 16);  // sum of d1

        if (lane == 0) {
            // var = max(sigmoid(z), eps): 1/var = 1 + e^{-z},
            // log var = -log(1 + e^{-z}) -- one exp + one log, no division.
            const float z = zfull;
            float logv, inv_v;
            if (z > Z_CLAMP) {
                const float e = __expf(-z);
                inv_v = 1.0f + e;
                logv  = -__logf(inv_v);
            } else {
                inv_v = 1.0f / EPS;
                logv  = LOG_EPS;
            }
            const float dy  = ycur - s;   // s on lane 0 = mu
            const float nll = 0.5f * (logv + dy * dy * inv_v) + HALF_LOG_2PI;
            atomicAdd(&out[j >> 11], nll);   // RED.ADD, no return needed
        }

        if (!have_next) break;
        #pragma unroll
        for (int i = 0; i < 8; i++) cur[i] = nxt[i];   // register rotate
        ycur = ynxt;
        j = jn;
    }
}

extern "C" void kernel_launch(void* const* d_in, const int* in_sizes, int n_in,
                              void* d_out, int out_size) {
    const float* y    = (const float*)d_in[0];   // (T, N)
    const float* x    = (const float*)d_in[1];   // (T, N, D)
    const float* W    = (const float*)d_in[2];   // (2, D)
    const int*   lens = (const int*)d_in[3];     // (N,)
    float* out = (float*)d_out;                  // (N,)

    zero_out_kernel<<<1, 64>>>(out, out_size);

    gaussian_nll_kernel<<<NCTA, 256>>>(y, x, W, lens, out);
}